// round 10
// baseline (speedup 1.0000x reference)
#include <cuda_runtime.h>
#include <cuda_fp16.h>

#define N_NODES 100000
#define N_EDGES 1600000
#define F 64
#define SCAN_B 512
#define N_SCANB ((N_NODES + SCAN_B - 1) / SCAN_B)   // 196
#define NB_BUILD 296                                 // 2 blocks x 148 SMs, all resident

// ---- scratch (static __device__, no allocation) ----
__device__ unsigned g_barGen = 0;
__device__ unsigned g_barCnt = 0;
__device__ int     g_indeg[N_NODES];
__device__ int     g_start[N_NODES];       // local-exclusive (within 512-chunk)
__device__ int     g_cur[N_NODES];         // local bump counters
__device__ int     g_bsum[SCAN_B];
__device__ int     g_boff[SCAN_B];         // exclusive chunk offsets
__device__ float   g_dinv[N_NODES];
__device__ int     g_csr[N_EDGES];         // src node per CSR slot (grouped by dst)
__device__ __half2 g_hsh[N_NODES * 32];    // RAW (x @ W), fp16 pairs (no dinv!)
__device__ float   g_z[N_NODES * F];       // layer-1 activations (fp32)

// ---------------------------------------------------------------------------
// Software grid barrier. Safe: grid = NB_BUILD = 2/SM guaranteed resident
// (512 thr, <=64 regs via launch_bounds, 2KB smem).
// ---------------------------------------------------------------------------
__device__ __forceinline__ void gbar() {
    __syncthreads();
    __threadfence();
    if (threadIdx.x == 0) {
        unsigned gen = atomicAdd(&g_barGen, 0u);
        if (atomicAdd(&g_barCnt, 1u) == NB_BUILD - 1u) {
            g_barCnt = 0;
            __threadfence();
            atomicExch(&g_barGen, gen + 1u);
        } else {
            while (atomicAdd(&g_barGen, 0u) == gen) { __nanosleep(64); }
        }
    }
    __syncthreads();
}

// ---------------------------------------------------------------------------
// Persistent CSR build: zero -> count -> scan -> chunk-offset scan -> fill.
// Edge index is int32 (established empirically; guards keep wrongness visible
// as rel_err, never as corruption).
// ---------------------------------------------------------------------------
__global__ void __launch_bounds__(512, 2) k_build(const int* __restrict__ ei) {
    __shared__ int sh[SCAN_B];
    const int tid = threadIdx.x;
    const int gtid = blockIdx.x * 512 + tid;
    const int gstride = NB_BUILD * 512;

    // P0: zero indeg
    for (int i = gtid; i < N_NODES; i += gstride) g_indeg[i] = 0;
    gbar();

    // P1: count in-degrees
    for (int e = gtid; e < N_EDGES; e += gstride) {
        int d = ei[N_EDGES + e];
        if ((unsigned)d < N_NODES) atomicAdd(&g_indeg[d], 1);
    }
    gbar();

    // P2: per-512-chunk exclusive scan (+dinv, +cur init)
    if (blockIdx.x < N_SCANB) {
        int i = blockIdx.x * SCAN_B + tid;
        int v = (i < N_NODES) ? g_indeg[i] : 0;
        sh[tid] = v;
        __syncthreads();
        for (int off = 1; off < SCAN_B; off <<= 1) {
            int t = (tid >= off) ? sh[tid - off] : 0;
            __syncthreads();
            sh[tid] += t;
            __syncthreads();
        }
        if (i < N_NODES) {
            int ex = sh[tid] - v;
            g_start[i] = ex;
            g_cur[i]   = ex;
            g_dinv[i]  = rsqrtf((float)(v + 1));   // +1 self loop
        }
        if (tid == SCAN_B - 1) g_bsum[blockIdx.x] = sh[SCAN_B - 1];
    }
    gbar();

    // P3: block 0 scans the chunk sums
    if (blockIdx.x == 0) {
        int bv = (tid < N_SCANB) ? g_bsum[tid] : 0;
        sh[tid] = bv;
        __syncthreads();
        for (int off = 1; off < SCAN_B; off <<= 1) {
            int t = (tid >= off) ? sh[tid - off] : 0;
            __syncthreads();
            sh[tid] += t;
            __syncthreads();
        }
        if (tid < N_SCANB) g_boff[tid] = sh[tid] - bv;
    }
    gbar();

    // P4: fill CSR
    for (int e = gtid; e < N_EDGES; e += gstride) {
        int s = ei[e];
        int d = ei[N_EDGES + e];
        if ((unsigned)s < N_NODES && (unsigned)d < N_NODES) {
            int slot = atomicAdd(&g_cur[d], 1) + g_boff[d >> 9];
            if ((unsigned)slot < N_EDGES) g_csr[slot] = s;
        }
    }
}

// ---------------------------------------------------------------------------
// Tensor-core GEMM (tf32 m16n8k8): hraw = X @ W, stored fp16 (NO dinv — this
// kernel has zero dependency on the CSR build and forks at t=0).
// 64x64 tile, 256 threads = 8 warps; warp w: rows (w&3)*16, cols (w>>2)*32.
// Pitches: Xs 68 (bank 4r+c bijective), Ws 72 (bank 8k+n bijective).
//   L == 0: X = harness input (raw h);  L == 1: X = g_z (device symbol)
// ---------------------------------------------------------------------------
#define XP 68
#define WP 72

__device__ __forceinline__ unsigned f2tf32(float f) {
    unsigned r;
    asm("cvt.rna.tf32.f32 %0, %1;" : "=r"(r) : "f"(f));
    return r;
}

template <int L>
__global__ void __launch_bounds__(256) k_gemm(const float* __restrict__ Xin,
                                              const float* __restrict__ W) {
    __shared__ unsigned Xs[64 * XP];
    __shared__ unsigned Ws[64 * WP];

    const float* __restrict__ X = (L == 0) ? Xin : (const float*)g_z;

    const int tid = threadIdx.x;
    const int rowbase = blockIdx.x * 64;

    #pragma unroll
    for (int i = tid; i < 64 * 64; i += 256) {
        int k = i >> 6, n = i & 63;
        Ws[k * WP + n] = f2tf32(W[i]);
    }
    #pragma unroll
    for (int i = tid; i < 64 * 64; i += 256) {
        int r = i >> 6, c = i & 63;
        int row = rowbase + r;
        float v = (row < N_NODES) ? X[row * 64 + c] : 0.0f;
        Xs[r * XP + c] = f2tf32(v);
    }
    __syncthreads();

    const int warp = tid >> 5;
    const int lane = tid & 31;
    const int gid  = lane >> 2;
    const int tg   = lane & 3;
    const int wr   = (warp & 3) * 16;
    const int wc   = (warp >> 2) * 32;

    float4 acc[4] = {{0,0,0,0},{0,0,0,0},{0,0,0,0},{0,0,0,0}};

    #pragma unroll
    for (int kb = 0; kb < 64; kb += 8) {
        const unsigned* xrow = &Xs[(wr + gid) * XP + kb + tg];
        unsigned a0 = xrow[0];
        unsigned a1 = xrow[8 * XP];
        unsigned a2 = xrow[4];
        unsigned a3 = xrow[8 * XP + 4];
        #pragma unroll
        for (int t = 0; t < 4; t++) {
            const unsigned* wcol = &Ws[(kb + tg) * WP + wc + t * 8 + gid];
            unsigned b0 = wcol[0];
            unsigned b1 = wcol[4 * WP];
            asm volatile(
                "mma.sync.aligned.m16n8k8.row.col.f32.tf32.tf32.f32 "
                "{%0,%1,%2,%3}, {%4,%5,%6,%7}, {%8,%9}, {%0,%1,%2,%3};"
                : "+f"(acc[t].x), "+f"(acc[t].y), "+f"(acc[t].z), "+f"(acc[t].w)
                : "r"(a0), "r"(a1), "r"(a2), "r"(a3), "r"(b0), "r"(b1));
        }
    }

    const int r0 = rowbase + wr + gid;
    const int r1 = r0 + 8;
    #pragma unroll
    for (int t = 0; t < 4; t++) {
        int slot = (wc >> 1) + t * 4 + tg;
        if (r0 < N_NODES)
            g_hsh[r0 * 32 + slot] = __floats2half2_rn(acc[t].x, acc[t].y);
        if (r1 < N_NODES)
            g_hsh[r1 * 32 + slot] = __floats2half2_rn(acc[t].z, acc[t].w);
    }
}

// ---------------------------------------------------------------------------
// z[d] = relu( dinv_d * ( dinv_d*hraw[d] + Σ_s dinv_s*hraw[s] ) + b )
// One warp per node; lane owns half2 slot; dinv[s] is a lane-uniform broadcast
// load. FUSE_OUT == 1: fused linear readout into d_out.
// ---------------------------------------------------------------------------
template <int FUSE_OUT>
__global__ void __launch_bounds__(256) k_aggregate(const float* __restrict__ b,
                                                   const float* __restrict__ Wo,
                                                   const float* __restrict__ bo,
                                                   float* __restrict__ out) {
    const int t = blockIdx.x * blockDim.x + threadIdx.x;
    const int node = t >> 5;
    if (node >= N_NODES) return;
    const int lane = t & 31;

    const float di = g_dinv[node];
    float2 self = __half22float2(g_hsh[node * 32 + lane]);
    float2 acc = make_float2(self.x * di, self.y * di);   // self loop (dinv_d)

    int e   = g_start[node] + g_boff[node >> 9];
    const int end = e + g_indeg[node];

    for (; e + 4 <= end; e += 4) {
        int s0 = __ldg(&g_csr[e]);
        int s1 = __ldg(&g_csr[e + 1]);
        int s2 = __ldg(&g_csr[e + 2]);
        int s3 = __ldg(&g_csr[e + 3]);
        float d0 = __ldg(&g_dinv[s0]);
        float d1 = __ldg(&g_dinv[s1]);
        float d2 = __ldg(&g_dinv[s2]);
        float d3 = __ldg(&g_dinv[s3]);
        float2 v0 = __half22float2(__ldg(&g_hsh[s0 * 32 + lane]));
        float2 v1 = __half22float2(__ldg(&g_hsh[s1 * 32 + lane]));
        float2 v2 = __half22float2(__ldg(&g_hsh[s2 * 32 + lane]));
        float2 v3 = __half22float2(__ldg(&g_hsh[s3 * 32 + lane]));
        acc.x += d0 * v0.x + d1 * v1.x + d2 * v2.x + d3 * v3.x;
        acc.y += d0 * v0.y + d1 * v1.y + d2 * v2.y + d3 * v3.y;
    }
    for (; e < end; e++) {
        int s = __ldg(&g_csr[e]);
        float ds = __ldg(&g_dinv[s]);
        float2 v = __half22float2(__ldg(&g_hsh[s * 32 + lane]));
        acc.x += ds * v.x; acc.y += ds * v.y;
    }

    const int c = lane * 2;
    float2 bb = *(const float2*)(b + c);
    float zx = fmaxf(acc.x * di + bb.x, 0.0f);
    float zy = fmaxf(acc.y * di + bb.y, 0.0f);

    if constexpr (FUSE_OUT == 0) {
        *(float2*)(g_z + node * 64 + c) = make_float2(zx, zy);
    } else {
        float2 w = *(const float2*)(Wo + c);
        float sum = zx * w.x + zy * w.y;
        #pragma unroll
        for (int off = 16; off; off >>= 1)
            sum += __shfl_down_sync(0xffffffff, sum, off);
        if (lane == 0) out[node] = sum + bo[0];
    }
}

// ---------------------------------------------------------------------------
extern "C" void kernel_launch(void* const* d_in, const int* in_sizes, int n_in,
                              void* d_out, int out_size) {
    const float* h  = (const float*)d_in[0];
    const int*   ei = (const int*)d_in[1];   // int32 [2,E] (empirically established)
    const float* W1 = (const float*)d_in[2];
    const float* b1 = (const float*)d_in[3];
    const float* W2 = (const float*)d_in[4];
    const float* b2 = (const float*)d_in[5];
    const float* Wo = (const float*)d_in[6];
    const float* bo = (const float*)d_in[7];
    float* out = (float*)d_out;

    cudaStream_t s2;
    cudaStreamCreateWithFlags(&s2, cudaStreamNonBlocking);
    cudaEvent_t eFork, eJoin;
    cudaEventCreateWithFlags(&eFork, cudaEventDisableTiming);
    cudaEventCreateWithFlags(&eJoin, cudaEventDisableTiming);

    // Fork gemm0 at t=0 — it has no dependency on the CSR build anymore.
    cudaEventRecord(eFork, 0);
    cudaStreamWaitEvent(s2, eFork, 0);
    k_gemm<0><<<(N_NODES + 63) / 64, 256, 0, s2>>>(h, W1);
    cudaEventRecord(eJoin, s2);

    // Main stream: single persistent CSR-build kernel.
    k_build<<<NB_BUILD, 512>>>(ei);

    cudaStreamWaitEvent(0, eJoin, 0);
    k_aggregate<0><<<(N_NODES * 32 + 255) / 256, 256>>>(b1, nullptr, nullptr, nullptr);
    k_gemm<1><<<(N_NODES + 63) / 64, 256>>>(nullptr, W2);
    k_aggregate<1><<<(N_NODES * 32 + 255) / 256, 256>>>(b2, Wo, bo, out);

    cudaEventDestroy(eFork);
    cudaEventDestroy(eJoin);
    cudaStreamDestroy(s2);
}

// round 11
// speedup vs baseline: 1.3403x; 1.3403x over previous
#include <cuda_runtime.h>
#include <cuda_fp16.h>

#define N_NODES 100000
#define N_EDGES 1600000
#define F 64
#define SCAN_B 512
#define N_SCANB ((N_NODES + SCAN_B - 1) / SCAN_B)   // 196

// ---- scratch (static __device__, no allocation) ----
__device__ int     g_done;                 // last-block-done counter for the scan
__device__ int     g_indeg[N_NODES];
__device__ int     g_start[N_NODES];       // local-exclusive (within 512-chunk)
__device__ int     g_cur[N_NODES];         // local bump counters
__device__ int     g_bsum[SCAN_B];
__device__ int     g_boff[SCAN_B];         // exclusive chunk offsets
__device__ float   g_dinv[N_NODES];
__device__ int     g_csr[N_EDGES];         // src node per CSR slot (grouped by dst)
__device__ __half2 g_hsh[N_NODES * 32];    // RAW (x @ W), fp16 pairs (no dinv)
__device__ float   g_z[N_NODES * F];       // layer-1 activations (fp32)

// ---------------------------------------------------------------------------
__global__ void k_init() {
    int i = blockIdx.x * blockDim.x + threadIdx.x;
    if (i < N_NODES) g_indeg[i] = 0;
    if (i == 0) g_done = 0;
}

__global__ void k_count(const int* __restrict__ ei) {
    int e = blockIdx.x * blockDim.x + threadIdx.x;
    if (e >= N_EDGES) return;
    int d = ei[N_EDGES + e];
    if ((unsigned)d < N_NODES) atomicAdd(&g_indeg[d], 1);
}

// ---------------------------------------------------------------------------
// Single-kernel scan (last-done-block pattern). Consumers add g_boff[node>>9].
// Classic launch — no cross-stream residency assumptions.
// ---------------------------------------------------------------------------
__global__ void __launch_bounds__(SCAN_B) k_scan() {
    __shared__ int sh[SCAN_B];
    __shared__ int amLast;
    int i = blockIdx.x * SCAN_B + threadIdx.x;
    int v = (i < N_NODES) ? g_indeg[i] : 0;
    sh[threadIdx.x] = v;
    __syncthreads();
    for (int off = 1; off < SCAN_B; off <<= 1) {
        int t = (threadIdx.x >= off) ? sh[threadIdx.x - off] : 0;
        __syncthreads();
        sh[threadIdx.x] += t;
        __syncthreads();
    }
    if (i < N_NODES) {
        int ex = sh[threadIdx.x] - v;
        g_start[i] = ex;
        g_cur[i]   = ex;
        g_dinv[i]  = rsqrtf((float)(v + 1));   // +1 self loop
    }
    if (threadIdx.x == SCAN_B - 1) g_bsum[blockIdx.x] = sh[SCAN_B - 1];
    __threadfence();
    __syncthreads();
    if (threadIdx.x == 0)
        amLast = (atomicAdd(&g_done, 1) == (int)gridDim.x - 1);
    __syncthreads();
    if (amLast) {
        __threadfence();
        int bv = (threadIdx.x < N_SCANB) ? g_bsum[threadIdx.x] : 0;
        sh[threadIdx.x] = bv;
        __syncthreads();
        for (int off = 1; off < SCAN_B; off <<= 1) {
            int t = (threadIdx.x >= off) ? sh[threadIdx.x - off] : 0;
            __syncthreads();
            sh[threadIdx.x] += t;
            __syncthreads();
        }
        if (threadIdx.x < N_SCANB) g_boff[threadIdx.x] = sh[threadIdx.x] - bv;
    }
}

__global__ void k_fill(const int* __restrict__ ei) {
    int e = blockIdx.x * blockDim.x + threadIdx.x;
    if (e >= N_EDGES) return;
    int s = ei[e];
    int d = ei[N_EDGES + e];
    if ((unsigned)s < N_NODES && (unsigned)d < N_NODES) {
        int slot = atomicAdd(&g_cur[d], 1) + g_boff[d >> 9];
        if ((unsigned)slot < N_EDGES) g_csr[slot] = s;
    }
}

// ---------------------------------------------------------------------------
// Tensor-core GEMM (tf32 m16n8k8): hraw = X @ W, fp16 store, NO dinv —
// zero dependency on the CSR build, so gemm0 forks at t=0.
// 64x64 tile, 256 threads = 8 warps. Pitches: Xs 68, Ws 72 (conflict-free).
//   L == 0: X = harness input (raw h);  L == 1: X = g_z (device symbol)
// ---------------------------------------------------------------------------
#define XP 68
#define WP 72

__device__ __forceinline__ unsigned f2tf32(float f) {
    unsigned r;
    asm("cvt.rna.tf32.f32 %0, %1;" : "=r"(r) : "f"(f));
    return r;
}

template <int L>
__global__ void __launch_bounds__(256) k_gemm(const float* __restrict__ Xin,
                                              const float* __restrict__ W) {
    __shared__ unsigned Xs[64 * XP];
    __shared__ unsigned Ws[64 * WP];

    const float* __restrict__ X = (L == 0) ? Xin : (const float*)g_z;

    const int tid = threadIdx.x;
    const int rowbase = blockIdx.x * 64;

    #pragma unroll
    for (int i = tid; i < 64 * 64; i += 256) {
        int k = i >> 6, n = i & 63;
        Ws[k * WP + n] = f2tf32(W[i]);
    }
    #pragma unroll
    for (int i = tid; i < 64 * 64; i += 256) {
        int r = i >> 6, c = i & 63;
        int row = rowbase + r;
        float v = (row < N_NODES) ? X[row * 64 + c] : 0.0f;
        Xs[r * XP + c] = f2tf32(v);
    }
    __syncthreads();

    const int warp = tid >> 5;
    const int lane = tid & 31;
    const int gid  = lane >> 2;
    const int tg   = lane & 3;
    const int wr   = (warp & 3) * 16;
    const int wc   = (warp >> 2) * 32;

    float4 acc[4] = {{0,0,0,0},{0,0,0,0},{0,0,0,0},{0,0,0,0}};

    #pragma unroll
    for (int kb = 0; kb < 64; kb += 8) {
        const unsigned* xrow = &Xs[(wr + gid) * XP + kb + tg];
        unsigned a0 = xrow[0];
        unsigned a1 = xrow[8 * XP];
        unsigned a2 = xrow[4];
        unsigned a3 = xrow[8 * XP + 4];
        #pragma unroll
        for (int t = 0; t < 4; t++) {
            const unsigned* wcol = &Ws[(kb + tg) * WP + wc + t * 8 + gid];
            unsigned b0 = wcol[0];
            unsigned b1 = wcol[4 * WP];
            asm volatile(
                "mma.sync.aligned.m16n8k8.row.col.f32.tf32.tf32.f32 "
                "{%0,%1,%2,%3}, {%4,%5,%6,%7}, {%8,%9}, {%0,%1,%2,%3};"
                : "+f"(acc[t].x), "+f"(acc[t].y), "+f"(acc[t].z), "+f"(acc[t].w)
                : "r"(a0), "r"(a1), "r"(a2), "r"(a3), "r"(b0), "r"(b1));
        }
    }

    const int r0 = rowbase + wr + gid;
    const int r1 = r0 + 8;
    #pragma unroll
    for (int t = 0; t < 4; t++) {
        int slot = (wc >> 1) + t * 4 + tg;
        if (r0 < N_NODES)
            g_hsh[r0 * 32 + slot] = __floats2half2_rn(acc[t].x, acc[t].y);
        if (r1 < N_NODES)
            g_hsh[r1 * 32 + slot] = __floats2half2_rn(acc[t].z, acc[t].w);
    }
}

// ---------------------------------------------------------------------------
// z[d] = relu( dinv_d * ( dinv_d*hraw[d] + Σ_s dinv_s*hraw[s] ) + b )
// One warp per node; lane owns half2 slot; dinv[s] lane-uniform broadcast.
// FUSE_OUT == 1: fused linear readout into d_out.
// ---------------------------------------------------------------------------
template <int FUSE_OUT>
__global__ void __launch_bounds__(256) k_aggregate(const float* __restrict__ b,
                                                   const float* __restrict__ Wo,
                                                   const float* __restrict__ bo,
                                                   float* __restrict__ out) {
    const int t = blockIdx.x * blockDim.x + threadIdx.x;
    const int node = t >> 5;
    if (node >= N_NODES) return;
    const int lane = t & 31;

    const float di = g_dinv[node];
    float2 self = __half22float2(g_hsh[node * 32 + lane]);
    float2 acc = make_float2(self.x * di, self.y * di);   // self loop

    int e   = g_start[node] + g_boff[node >> 9];
    const int end = e + g_indeg[node];

    for (; e + 4 <= end; e += 4) {
        int s0 = __ldg(&g_csr[e]);
        int s1 = __ldg(&g_csr[e + 1]);
        int s2 = __ldg(&g_csr[e + 2]);
        int s3 = __ldg(&g_csr[e + 3]);
        float d0 = __ldg(&g_dinv[s0]);
        float d1 = __ldg(&g_dinv[s1]);
        float d2 = __ldg(&g_dinv[s2]);
        float d3 = __ldg(&g_dinv[s3]);
        float2 v0 = __half22float2(__ldg(&g_hsh[s0 * 32 + lane]));
        float2 v1 = __half22float2(__ldg(&g_hsh[s1 * 32 + lane]));
        float2 v2 = __half22float2(__ldg(&g_hsh[s2 * 32 + lane]));
        float2 v3 = __half22float2(__ldg(&g_hsh[s3 * 32 + lane]));
        acc.x += d0 * v0.x + d1 * v1.x + d2 * v2.x + d3 * v3.x;
        acc.y += d0 * v0.y + d1 * v1.y + d2 * v2.y + d3 * v3.y;
    }
    for (; e < end; e++) {
        int s = __ldg(&g_csr[e]);
        float ds = __ldg(&g_dinv[s]);
        float2 v = __half22float2(__ldg(&g_hsh[s * 32 + lane]));
        acc.x += ds * v.x; acc.y += ds * v.y;
    }

    const int c = lane * 2;
    float2 bb = *(const float2*)(b + c);
    float zx = fmaxf(acc.x * di + bb.x, 0.0f);
    float zy = fmaxf(acc.y * di + bb.y, 0.0f);

    if constexpr (FUSE_OUT == 0) {
        *(float2*)(g_z + node * 64 + c) = make_float2(zx, zy);
    } else {
        float2 w = *(const float2*)(Wo + c);
        float sum = zx * w.x + zy * w.y;
        #pragma unroll
        for (int off = 16; off; off >>= 1)
            sum += __shfl_down_sync(0xffffffff, sum, off);
        if (lane == 0) out[node] = sum + bo[0];
    }
}

// ---------------------------------------------------------------------------
extern "C" void kernel_launch(void* const* d_in, const int* in_sizes, int n_in,
                              void* d_out, int out_size) {
    const float* h  = (const float*)d_in[0];
    const int*   ei = (const int*)d_in[1];   // int32 [2,E]
    const float* W1 = (const float*)d_in[2];
    const float* b1 = (const float*)d_in[3];
    const float* W2 = (const float*)d_in[4];
    const float* b2 = (const float*)d_in[5];
    const float* Wo = (const float*)d_in[6];
    const float* bo = (const float*)d_in[7];
    float* out = (float*)d_out;

    cudaStream_t s2;
    cudaStreamCreateWithFlags(&s2, cudaStreamNonBlocking);
    cudaEvent_t eFork, eJoin;
    cudaEventCreateWithFlags(&eFork, cudaEventDisableTiming);
    cudaEventCreateWithFlags(&eJoin, cudaEventDisableTiming);

    // Fork gemm0 at t=0 — no dependency on the CSR build (raw X@W, no dinv).
    cudaEventRecord(eFork, 0);
    cudaStreamWaitEvent(s2, eFork, 0);
    k_gemm<0><<<(N_NODES + 63) / 64, 256, 0, s2>>>(h, W1);
    cudaEventRecord(eJoin, s2);

    // Main stream: classic CSR build.
    k_init<<<(N_NODES + 255) / 256, 256>>>();
    k_count<<<(N_EDGES + 255) / 256, 256>>>(ei);
    k_scan<<<N_SCANB, SCAN_B>>>();
    k_fill<<<(N_EDGES + 255) / 256, 256>>>(ei);

    cudaStreamWaitEvent(0, eJoin, 0);
    k_aggregate<0><<<(N_NODES * 32 + 255) / 256, 256>>>(b1, nullptr, nullptr, nullptr);
    k_gemm<1><<<(N_NODES + 63) / 64, 256>>>(nullptr, W2);
    k_aggregate<1><<<(N_NODES * 32 + 255) / 256, 256>>>(b2, Wo, bo, out);

    cudaEventDestroy(eFork);
    cudaEventDestroy(eJoin);
    cudaStreamDestroy(s2);
}

// round 12
// speedup vs baseline: 1.5237x; 1.1368x over previous
#include <cuda_runtime.h>
#include <cuda_fp16.h>

#define N_NODES 100000
#define N_EDGES 1600000
#define F 64
#define SCAN_B 512
#define N_SCANB ((N_NODES + SCAN_B - 1) / SCAN_B)   // 196

// ---- scratch (static __device__, no allocation) ----
__device__ int     g_done;                 // last-block-done counter for the scan
__device__ int     g_indeg[N_NODES];
__device__ int     g_start[N_NODES];       // local-exclusive (within 512-chunk)
__device__ int     g_cur[N_NODES];         // local bump counters
__device__ int     g_bsum[SCAN_B];
__device__ int     g_boff[SCAN_B];         // exclusive chunk offsets
__device__ float   g_dinv[N_NODES];
__device__ int     g_csr[N_EDGES];         // src node per CSR slot (grouped by dst)
__device__ __half2 g_hsh[N_NODES * 32];    // messages, fp16 pairs
__device__ float   g_z[N_NODES * F];       // layer-1 activations (fp32)

// ---------------------------------------------------------------------------
__global__ void k_init() {
    int i = blockIdx.x * blockDim.x + threadIdx.x;
    if (i < N_NODES) g_indeg[i] = 0;
    if (i == 0) g_done = 0;
}

__global__ void k_count(const int* __restrict__ ei) {
    int e = blockIdx.x * blockDim.x + threadIdx.x;
    if (e >= N_EDGES) return;
    int d = ei[N_EDGES + e];
    if ((unsigned)d < N_NODES) atomicAdd(&g_indeg[d], 1);
}

// ---------------------------------------------------------------------------
// Single-kernel scan (last-done-block pattern). Consumers add g_boff[node>>9].
// ---------------------------------------------------------------------------
__global__ void __launch_bounds__(SCAN_B) k_scan() {
    __shared__ int sh[SCAN_B];
    __shared__ int amLast;
    int i = blockIdx.x * SCAN_B + threadIdx.x;
    int v = (i < N_NODES) ? g_indeg[i] : 0;
    sh[threadIdx.x] = v;
    __syncthreads();
    for (int off = 1; off < SCAN_B; off <<= 1) {
        int t = (threadIdx.x >= off) ? sh[threadIdx.x - off] : 0;
        __syncthreads();
        sh[threadIdx.x] += t;
        __syncthreads();
    }
    if (i < N_NODES) {
        int ex = sh[threadIdx.x] - v;
        g_start[i] = ex;
        g_cur[i]   = ex;
        g_dinv[i]  = rsqrtf((float)(v + 1));   // +1 self loop
    }
    if (threadIdx.x == SCAN_B - 1) g_bsum[blockIdx.x] = sh[SCAN_B - 1];
    __threadfence();
    __syncthreads();
    if (threadIdx.x == 0)
        amLast = (atomicAdd(&g_done, 1) == (int)gridDim.x - 1);
    __syncthreads();
    if (amLast) {
        __threadfence();
        int bv = (threadIdx.x < N_SCANB) ? g_bsum[threadIdx.x] : 0;
        sh[threadIdx.x] = bv;
        __syncthreads();
        for (int off = 1; off < SCAN_B; off <<= 1) {
            int t = (threadIdx.x >= off) ? sh[threadIdx.x - off] : 0;
            __syncthreads();
            sh[threadIdx.x] += t;
            __syncthreads();
        }
        if (threadIdx.x < N_SCANB) g_boff[threadIdx.x] = sh[threadIdx.x] - bv;
    }
}

__global__ void k_fill(const int* __restrict__ ei) {
    int e = blockIdx.x * blockDim.x + threadIdx.x;
    if (e >= N_EDGES) return;
    int s = ei[e];
    int d = ei[N_EDGES + e];
    if ((unsigned)s < N_NODES && (unsigned)d < N_NODES) {
        int slot = atomicAdd(&g_cur[d], 1) + g_boff[d >> 9];
        if ((unsigned)slot < N_EDGES) g_csr[slot] = s;
    }
}

// ---------------------------------------------------------------------------
// Per-node scale pass: g_hsh[row] *= dinv[row]. One thread = one uint4
// (4 half2 = 8 cols); 8 threads/row. Runs on s2 overlapped with k_fill.
// ---------------------------------------------------------------------------
__global__ void __launch_bounds__(256) k_scale() {
    int i = blockIdx.x * blockDim.x + threadIdx.x;          // uint4 index
    if (i >= N_NODES * 8) return;
    int row = i >> 3;
    float di = g_dinv[row];
    __half2 dh = __float2half2_rn(di);
    uint4 v = *(const uint4*)&g_hsh[(size_t)i * 4];
    __half2* p = (__half2*)&v;
    p[0] = __hmul2(p[0], dh);
    p[1] = __hmul2(p[1], dh);
    p[2] = __hmul2(p[2], dh);
    p[3] = __hmul2(p[3], dh);
    *(uint4*)&g_hsh[(size_t)i * 4] = v;
}

// ---------------------------------------------------------------------------
// Tensor-core GEMM (tf32 m16n8k8), fp16 store.
//   L == 0: X = raw h, epilogue stores RAW product (no dinv -> zero deps,
//           forked at t=0; dinv applied later by k_scale).
//   L == 1: X = g_z, epilogue applies dinv (available by then).
// 64x64 tile, 256 threads = 8 warps. Pitches: Xs 68, Ws 72 (conflict-free).
// ---------------------------------------------------------------------------
#define XP 68
#define WP 72

__device__ __forceinline__ unsigned f2tf32(float f) {
    unsigned r;
    asm("cvt.rna.tf32.f32 %0, %1;" : "=r"(r) : "f"(f));
    return r;
}

template <int L>
__global__ void __launch_bounds__(256) k_gemm(const float* __restrict__ Xin,
                                              const float* __restrict__ W) {
    __shared__ unsigned Xs[64 * XP];
    __shared__ unsigned Ws[64 * WP];

    const float* __restrict__ X = (L == 0) ? Xin : (const float*)g_z;

    const int tid = threadIdx.x;
    const int rowbase = blockIdx.x * 64;

    #pragma unroll
    for (int i = tid; i < 64 * 64; i += 256) {
        int k = i >> 6, n = i & 63;
        Ws[k * WP + n] = f2tf32(W[i]);
    }
    #pragma unroll
    for (int i = tid; i < 64 * 64; i += 256) {
        int r = i >> 6, c = i & 63;
        int row = rowbase + r;
        float v = (row < N_NODES) ? X[row * 64 + c] : 0.0f;
        Xs[r * XP + c] = f2tf32(v);
    }
    __syncthreads();

    const int warp = tid >> 5;
    const int lane = tid & 31;
    const int gid  = lane >> 2;
    const int tg   = lane & 3;
    const int wr   = (warp & 3) * 16;
    const int wc   = (warp >> 2) * 32;

    float4 acc[4] = {{0,0,0,0},{0,0,0,0},{0,0,0,0},{0,0,0,0}};

    #pragma unroll
    for (int kb = 0; kb < 64; kb += 8) {
        const unsigned* xrow = &Xs[(wr + gid) * XP + kb + tg];
        unsigned a0 = xrow[0];
        unsigned a1 = xrow[8 * XP];
        unsigned a2 = xrow[4];
        unsigned a3 = xrow[8 * XP + 4];
        #pragma unroll
        for (int t = 0; t < 4; t++) {
            const unsigned* wcol = &Ws[(kb + tg) * WP + wc + t * 8 + gid];
            unsigned b0 = wcol[0];
            unsigned b1 = wcol[4 * WP];
            asm volatile(
                "mma.sync.aligned.m16n8k8.row.col.f32.tf32.tf32.f32 "
                "{%0,%1,%2,%3}, {%4,%5,%6,%7}, {%8,%9}, {%0,%1,%2,%3};"
                : "+f"(acc[t].x), "+f"(acc[t].y), "+f"(acc[t].z), "+f"(acc[t].w)
                : "r"(a0), "r"(a1), "r"(a2), "r"(a3), "r"(b0), "r"(b1));
        }
    }

    const int r0 = rowbase + wr + gid;
    const int r1 = r0 + 8;
    float d0 = 1.0f, d1 = 1.0f;
    if (L == 1) {
        d0 = (r0 < N_NODES) ? g_dinv[r0] : 0.0f;
        d1 = (r1 < N_NODES) ? g_dinv[r1] : 0.0f;
    }
    #pragma unroll
    for (int t = 0; t < 4; t++) {
        int slot = (wc >> 1) + t * 4 + tg;
        if (r0 < N_NODES)
            g_hsh[r0 * 32 + slot] = __floats2half2_rn(acc[t].x * d0, acc[t].y * d0);
        if (r1 < N_NODES)
            g_hsh[r1 * 32 + slot] = __floats2half2_rn(acc[t].z * d1, acc[t].w * d1);
    }
}

// ---------------------------------------------------------------------------
// z[node] = relu( dinv[node] * (hs[node] + sum_{neigh} hs[s]) + b )
// hs already dinv[src]-scaled. One warp per node; lane owns half2 slot.
// FUSE_OUT == 1: fused linear readout into d_out.
// ---------------------------------------------------------------------------
template <int FUSE_OUT>
__global__ void __launch_bounds__(256) k_aggregate(const float* __restrict__ b,
                                                   const float* __restrict__ Wo,
                                                   const float* __restrict__ bo,
                                                   float* __restrict__ out) {
    const int t = blockIdx.x * blockDim.x + threadIdx.x;
    const int node = t >> 5;
    if (node >= N_NODES) return;
    const int lane = t & 31;

    float2 acc = __half22float2(g_hsh[node * 32 + lane]);  // self loop

    int e   = g_start[node] + g_boff[node >> 9];
    const int end = e + g_indeg[node];

    for (; e + 8 <= end; e += 8) {
        int s0 = __ldg(&g_csr[e]);
        int s1 = __ldg(&g_csr[e + 1]);
        int s2 = __ldg(&g_csr[e + 2]);
        int s3 = __ldg(&g_csr[e + 3]);
        int s4 = __ldg(&g_csr[e + 4]);
        int s5 = __ldg(&g_csr[e + 5]);
        int s6 = __ldg(&g_csr[e + 6]);
        int s7 = __ldg(&g_csr[e + 7]);
        float2 v0 = __half22float2(__ldg(&g_hsh[s0 * 32 + lane]));
        float2 v1 = __half22float2(__ldg(&g_hsh[s1 * 32 + lane]));
        float2 v2 = __half22float2(__ldg(&g_hsh[s2 * 32 + lane]));
        float2 v3 = __half22float2(__ldg(&g_hsh[s3 * 32 + lane]));
        float2 v4 = __half22float2(__ldg(&g_hsh[s4 * 32 + lane]));
        float2 v5 = __half22float2(__ldg(&g_hsh[s5 * 32 + lane]));
        float2 v6 = __half22float2(__ldg(&g_hsh[s6 * 32 + lane]));
        float2 v7 = __half22float2(__ldg(&g_hsh[s7 * 32 + lane]));
        acc.x += ((v0.x + v1.x) + (v2.x + v3.x)) + ((v4.x + v5.x) + (v6.x + v7.x));
        acc.y += ((v0.y + v1.y) + (v2.y + v3.y)) + ((v4.y + v5.y) + (v6.y + v7.y));
    }
    for (; e < end; e++) {
        int s = __ldg(&g_csr[e]);
        float2 v = __half22float2(__ldg(&g_hsh[s * 32 + lane]));
        acc.x += v.x; acc.y += v.y;
    }

    const float di = g_dinv[node];
    const int c = lane * 2;
    float2 bb = *(const float2*)(b + c);
    float zx = fmaxf(acc.x * di + bb.x, 0.0f);
    float zy = fmaxf(acc.y * di + bb.y, 0.0f);

    if constexpr (FUSE_OUT == 0) {
        *(float2*)(g_z + node * 64 + c) = make_float2(zx, zy);
    } else {
        float2 w = *(const float2*)(Wo + c);
        float sum = zx * w.x + zy * w.y;
        #pragma unroll
        for (int off = 16; off; off >>= 1)
            sum += __shfl_down_sync(0xffffffff, sum, off);
        if (lane == 0) out[node] = sum + bo[0];
    }
}

// ---------------------------------------------------------------------------
extern "C" void kernel_launch(void* const* d_in, const int* in_sizes, int n_in,
                              void* d_out, int out_size) {
    const float* h  = (const float*)d_in[0];
    const int*   ei = (const int*)d_in[1];   // int32 [2,E]
    const float* W1 = (const float*)d_in[2];
    const float* b1 = (const float*)d_in[3];
    const float* W2 = (const float*)d_in[4];
    const float* b2 = (const float*)d_in[5];
    const float* Wo = (const float*)d_in[6];
    const float* bo = (const float*)d_in[7];
    float* out = (float*)d_out;

    cudaStream_t s2;
    cudaStreamCreateWithFlags(&s2, cudaStreamNonBlocking);
    cudaEvent_t eFork, eScan, eJoin;
    cudaEventCreateWithFlags(&eFork, cudaEventDisableTiming);
    cudaEventCreateWithFlags(&eScan, cudaEventDisableTiming);
    cudaEventCreateWithFlags(&eJoin, cudaEventDisableTiming);

    // s2: gemm0 (raw h@W1, zero deps) at t=0.
    cudaEventRecord(eFork, 0);
    cudaStreamWaitEvent(s2, eFork, 0);
    k_gemm<0><<<(N_NODES + 63) / 64, 256, 0, s2>>>(h, W1);

    // main: CSR build front half.
    k_init<<<(N_NODES + 255) / 256, 256>>>();
    k_count<<<(N_EDGES + 255) / 256, 256>>>(ei);
    k_scan<<<N_SCANB, SCAN_B>>>();
    cudaEventRecord(eScan, 0);

    // s2: scale pass (needs gemm0 + scan's dinv); overlaps k_fill on main.
    cudaStreamWaitEvent(s2, eScan, 0);
    k_scale<<<(N_NODES * 8 + 255) / 256, 256, 0, s2>>>();
    cudaEventRecord(eJoin, s2);

    k_fill<<<(N_EDGES + 255) / 256, 256>>>(ei);

    cudaStreamWaitEvent(0, eJoin, 0);
    k_aggregate<0><<<(N_NODES * 32 + 255) / 256, 256>>>(b1, nullptr, nullptr, nullptr);
    k_gemm<1><<<(N_NODES + 63) / 64, 256>>>(nullptr, W2);
    k_aggregate<1><<<(N_NODES * 32 + 255) / 256, 256>>>(b2, Wo, bo, out);

    cudaEventDestroy(eFork);
    cudaEventDestroy(eScan);
    cudaEventDestroy(eJoin);
    cudaStreamDestroy(s2);
}